// round 4
// baseline (speedup 1.0000x reference)
#include <cuda_runtime.h>
#include <math.h>

#define NUM_NEURONS 2048
#define D_MODEL     1024
#define BATCH       64
#define KSPLIT      16
#define KCHUNK      256          // K rows per GEMM CTA (4096/16)
#define DCHUNK      128

// Scratch (static device globals — no runtime allocation)
__device__ __align__(16) float g_xT[D_MODEL * BATCH];             // x transposed [d][b]
__device__ __align__(16) float g_S[2 * NUM_NEURONS * BATCH];      // sums [k][b]: cos rows then sin rows
__device__ __align__(16) float g_part[KSPLIT * BATCH * D_MODEL];  // GEMM partials (4MB)

// ---------------------------------------------------------------------------
// Transpose x -> [d][b] so main-kernel shared stage is coalesced.
// ---------------------------------------------------------------------------
__global__ void prep_x(const float* __restrict__ x) {
    int i = blockIdx.x * 256 + threadIdx.x;   // 65536 total
    g_xT[(i & 1023) * BATCH + (i >> 10)] = x[i];
}

// ---------------------------------------------------------------------------
// FMA-pipe sincos: magic-number quadrant reduction; economized deg5 sin /
// deg4 cos on u in [-0.5, 0.5] quarter-turns. Abs err <= ~1.4e-5 (budget is
// 1e-3 on the output; contribution ~1e-5 rel). 10 fma-class ops.
// ---------------------------------------------------------------------------
__device__ __forceinline__ void sincos_poly(float th, float& s_out, float& c_out) {
    const float TWO_OVER_PI = 0.636619772f;
    const float MAGIC = 12582912.0f;       // 1.5 * 2^23
    float w   = th * TWO_OVER_PI;          // quarter-turns
    float big = w + MAGIC;                 // round-to-nearest-even
    int   qi  = __float_as_int(big);       // low mantissa bits = q mod 4
    float r   = big - MAGIC;
    float u   = w - r;                     // [-0.5, 0.5]
    float u2  = u * u;
    // sin(u*pi/2): economized deg5
    float sp  = fmaf(u2, fmaf(u2, 0.077644356f, -0.64570806f), 1.57078833f) * u;
    // cos(u*pi/2): economized deg4
    float cp  = fmaf(u2, fmaf(u2, 0.24584570f, -1.23296711f), 0.99998981f);
    float ss = (qi & 1) ? cp : sp;
    float cc = (qi & 1) ? sp : cp;
    if (qi & 2)       ss = -ss;
    if ((qi + 1) & 2) cc = -cc;
    s_out = ss; c_out = cc;
}

// ---------------------------------------------------------------------------
// Main: per CTA, 2 neurons x all 64 batches; d-loop staged through shared.
// Dual-path sincos: 11/16 MUFU, 5/16 FMA-pipe poly (pipe-balance point for
// the 10-fma poly).
// ---------------------------------------------------------------------------
__global__ __launch_bounds__(128) void resonant_main(const float* __restrict__ t,
                                                     const float* __restrict__ W,
                                                     const float* __restrict__ Bp) {
    __shared__ float  x_sh[DCHUNK][BATCH];   // 32 KB, lane=b conflict-free
    __shared__ float2 rB_sh[2][DCHUNK];      // 2 KB, warp-broadcast reads

    int tid = threadIdx.x;
    int b   = tid & 63;
    int nl  = tid >> 6;
    int n0  = blockIdx.x * 2;

    float tb = t[b];
    float cs = 0.0f, sn = 0.0f;

    for (int d0 = 0; d0 < D_MODEL; d0 += DCHUNK) {
        float4*       xs4 = reinterpret_cast<float4*>(&x_sh[0][0]);
        const float4* xg4 = reinterpret_cast<const float4*>(g_xT + d0 * BATCH);
        #pragma unroll
        for (int i = 0; i < (DCHUNK * BATCH / 4) / 128; i++)
            xs4[tid + i * 128] = xg4[tid + i * 128];
        {
            float w0 = W [(n0 + 0) * D_MODEL + d0 + tid];
            float p0 = Bp[(n0 + 0) * D_MODEL + d0 + tid];
            rB_sh[0][tid] = make_float2(__fdividef(1.0f, 1.0f + fabsf(w0)), p0);
            float w1 = W [(n0 + 1) * D_MODEL + d0 + tid];
            float p1 = Bp[(n0 + 1) * D_MODEL + d0 + tid];
            rB_sh[1][tid] = make_float2(__fdividef(1.0f, 1.0f + fabsf(w1)), p1);
        }
        __syncthreads();

        #pragma unroll
        for (int blk = 0; blk < DCHUNK; blk += 16) {
            #pragma unroll
            for (int j = 0; j < 16; j++) {
                float2 rb = rB_sh[nl][blk + j];
                float th  = fmaf(x_sh[blk + j][b], rb.x, rb.y) + tb;
                float s, c;
                if (j < 5) sincos_poly(th, s, c);   // FMA pipe
                else       __sincosf(th, &s, &c);   // MUFU pipe
                cs += c; sn += s;
            }
        }
        __syncthreads();
    }

    int n = n0 + nl;
    g_S[n * BATCH + b]                 = cs;  // cos row: k = n
    g_S[(n + NUM_NEURONS) * BATCH + b] = sn;  // sin row: k = n + 2048
}

// ---------------------------------------------------------------------------
// GEMM: C[b][j] = sum_k S[k][b] * Pcat[j][k], K=4096 split 16 ways.
// 64x64 tile, 4x4 register tile, register double-buffered global staging.
// Partials disjoint per (jt, ks) -> deterministic, no atomics.
// ---------------------------------------------------------------------------
__global__ __launch_bounds__(256) void gemm_kernel(const float* __restrict__ Pr,
                                                   const float* __restrict__ Pi) {
    __shared__ float S_sh[32][64];
    __shared__ float P_sh[32][68];   // padded rows, 16B-aligned

    int tid = threadIdx.x;
    int tx  = tid & 15;   // j groups of 4
    int ty  = tid >> 4;   // b groups of 4
    int j0  = blockIdx.x * 64;
    int k0  = blockIdx.y * KCHUNK;

    const float* P     = (k0 < NUM_NEURONS) ? Pr : Pi;
    int          kbase = (k0 < NUM_NEURONS) ? k0 : k0 - NUM_NEURONS;

    int s_lin = tid;          // 2 float4 per thread for S stage
    int jl    = tid >> 2;     // P stage: one j row, 8 contiguous k
    int kk0   = (tid & 3) * 8;

    float4 sA, sB, pA, pB;
    {   // preload chunk 0
        const float4* sg = reinterpret_cast<const float4*>(g_S + k0 * BATCH);
        sA = sg[s_lin]; sB = sg[s_lin + 256];
        const float4* pg = reinterpret_cast<const float4*>(
            P + (j0 + jl) * NUM_NEURONS + kbase + kk0);
        pA = pg[0]; pB = pg[1];
    }

    float acc[4][4] = {};

    #pragma unroll
    for (int kc = 0; kc < KCHUNK; kc += 32) {
        __syncthreads();
        reinterpret_cast<float4*>(&S_sh[0][0])[s_lin]       = sA;
        reinterpret_cast<float4*>(&S_sh[0][0])[s_lin + 256] = sB;
        P_sh[kk0 + 0][jl] = pA.x; P_sh[kk0 + 1][jl] = pA.y;
        P_sh[kk0 + 2][jl] = pA.z; P_sh[kk0 + 3][jl] = pA.w;
        P_sh[kk0 + 4][jl] = pB.x; P_sh[kk0 + 5][jl] = pB.y;
        P_sh[kk0 + 6][jl] = pB.z; P_sh[kk0 + 7][jl] = pB.w;
        __syncthreads();

        if (kc + 32 < KCHUNK) {   // prefetch next chunk into registers
            const float4* sg = reinterpret_cast<const float4*>(g_S + (k0 + kc + 32) * BATCH);
            sA = sg[s_lin]; sB = sg[s_lin + 256];
            const float4* pg = reinterpret_cast<const float4*>(
                P + (j0 + jl) * NUM_NEURONS + kbase + kc + 32 + kk0);
            pA = pg[0]; pB = pg[1];
        }

        #pragma unroll
        for (int kk = 0; kk < 32; kk++) {
            float4 a = *reinterpret_cast<const float4*>(&S_sh[kk][ty * 4]);
            float4 p = *reinterpret_cast<const float4*>(&P_sh[kk][tx * 4]);
            float av[4] = {a.x, a.y, a.z, a.w};
            float pv[4] = {p.x, p.y, p.z, p.w};
            #pragma unroll
            for (int ii = 0; ii < 4; ii++)
                #pragma unroll
                for (int jj = 0; jj < 4; jj++)
                    acc[ii][jj] = fmaf(av[ii], pv[jj], acc[ii][jj]);
        }
    }

    float* dst = g_part + blockIdx.y * (BATCH * D_MODEL);
    #pragma unroll
    for (int ii = 0; ii < 4; ii++) {
        float4 v = make_float4(acc[ii][0], acc[ii][1], acc[ii][2], acc[ii][3]);
        *reinterpret_cast<float4*>(dst + (ty * 4 + ii) * D_MODEL + j0 + tx * 4) = v;
    }
}

// ---------------------------------------------------------------------------
// Epilogue: reduce K-split partials + SiLU. float4 per thread, MLP=16.
// ---------------------------------------------------------------------------
__global__ __launch_bounds__(256) void epilogue(float* __restrict__ out) {
    int i4 = blockIdx.x * 256 + threadIdx.x;   // 16384 float4 outputs
    float4 s = make_float4(0.f, 0.f, 0.f, 0.f);
    #pragma unroll
    for (int ks = 0; ks < KSPLIT; ks++) {
        float4 v = reinterpret_cast<const float4*>(g_part + ks * (BATCH * D_MODEL))[i4];
        s.x += v.x; s.y += v.y; s.z += v.z; s.w += v.w;
    }
    float4 o;
    o.x = s.x / (1.0f + expf(-s.x));
    o.y = s.y / (1.0f + expf(-s.y));
    o.z = s.z / (1.0f + expf(-s.z));
    o.w = s.w / (1.0f + expf(-s.w));
    reinterpret_cast<float4*>(out)[i4] = o;
}

// ---------------------------------------------------------------------------
// Inputs: x, t, W, B_p, proj_real_w, proj_imag_w, sin_table, cos_table.
// Tables unused: HW sincos / poly within ~1.4e-5 abs of the LUT-lerp ref.
// Single stream (R2: chunked multi-stream overlap destroyed occupancy).
// ---------------------------------------------------------------------------
extern "C" void kernel_launch(void* const* d_in, const int* in_sizes, int n_in,
                              void* d_out, int out_size) {
    const float* x  = (const float*)d_in[0];
    const float* t  = (const float*)d_in[1];
    const float* W  = (const float*)d_in[2];
    const float* Bp = (const float*)d_in[3];
    const float* Pr = (const float*)d_in[4];
    const float* Pi = (const float*)d_in[5];
    float* out = (float*)d_out;

    prep_x<<<(BATCH * D_MODEL + 255) / 256, 256>>>(x);
    resonant_main<<<NUM_NEURONS / 2, 128>>>(t, W, Bp);
    dim3 gg(D_MODEL / 64, KSPLIT);
    gemm_kernel<<<gg, 256>>>(Pr, Pi);
    epilogue<<<(BATCH * D_MODEL / 4 + 255) / 256, 256>>>(out);
}

// round 5
// speedup vs baseline: 1.0216x; 1.0216x over previous
#include <cuda_runtime.h>
#include <math.h>

#define NUM_NEURONS 2048
#define D_MODEL     1024
#define BATCH       64
#define KSPLIT      32
#define KCHUNK      128          // K rows per GEMM CTA
#define DCHUNK      128

// Scratch (static device globals — no runtime allocation)
__device__ __align__(16) float g_xT[D_MODEL * BATCH];             // x transposed [d][b]
__device__ __align__(16) float g_S[2 * NUM_NEURONS * BATCH];      // sums [k][b]: cos rows then sin rows
__device__ __align__(16) float g_part[KSPLIT * BATCH * D_MODEL];  // GEMM partials (8MB)

// ---------------------------------------------------------------------------
// Transpose x -> [d][b] so main-kernel shared stage is coalesced.
// ---------------------------------------------------------------------------
__global__ void prep_x(const float* __restrict__ x) {
    int i = blockIdx.x * 256 + threadIdx.x;   // 65536 total
    g_xT[(i & 1023) * BATCH + (i >> 10)] = x[i];
}

// ---------------------------------------------------------------------------
// FMA-pipe sincos: quadrant reduction via magic-number round; Taylor deg7/deg6
// on phi in [-pi/4, pi/4]. Abs err <= ~4e-6. Runs entirely on fma/alu pipes,
// in parallel with MUFU-path elements. (R3-proven variant.)
// ---------------------------------------------------------------------------
__device__ __forceinline__ void sincos_poly(float th, float& s_out, float& c_out) {
    const float TWO_OVER_PI = 0.636619772f;
    const float MAGIC = 12582912.0f;       // 1.5 * 2^23
    float w   = th * TWO_OVER_PI;          // quarter-turns
    float big = w + MAGIC;                 // round-to-nearest-even
    int   qi  = __float_as_int(big);       // low mantissa bits = q mod 4
    float r   = big - MAGIC;
    float u   = w - r;                     // [-0.5, 0.5]
    float u2  = u * u;
    float sp  = fmaf(u2, fmaf(u2, fmaf(u2, -4.6817541e-3f, 7.9692626e-2f),
                              -6.4596410e-1f), 1.57079633f) * u;   // sin(u*pi/2)
    float cp  = fmaf(u2, fmaf(u2, fmaf(u2, -2.0864648e-2f, 2.5369510e-1f),
                              -1.2337006f), 1.0f);                 // cos(u*pi/2)
    float ss = (qi & 1) ? cp : sp;
    float cc = (qi & 1) ? sp : cp;
    if (qi & 2)       ss = -ss;
    if ((qi + 1) & 2) cc = -cc;
    s_out = ss; c_out = cc;
}

// ---------------------------------------------------------------------------
// Main: per CTA, 2 neurons x all 64 batches; d-loop staged through shared.
// Dual-path sincos: 3/4 MUFU, 1/4 FMA-pipe polynomial (R3-proven balance).
// ---------------------------------------------------------------------------
__global__ __launch_bounds__(128) void resonant_main(const float* __restrict__ t,
                                                     const float* __restrict__ W,
                                                     const float* __restrict__ Bp) {
    __shared__ float  x_sh[DCHUNK][BATCH];   // 32 KB, lane=b conflict-free
    __shared__ float2 rB_sh[2][DCHUNK];      // 2 KB, warp-broadcast reads

    int tid = threadIdx.x;
    int b   = tid & 63;
    int nl  = tid >> 6;
    int n0  = blockIdx.x * 2;

    float tb = t[b];
    float cs = 0.0f, sn = 0.0f;

    for (int d0 = 0; d0 < D_MODEL; d0 += DCHUNK) {
        float4*       xs4 = reinterpret_cast<float4*>(&x_sh[0][0]);
        const float4* xg4 = reinterpret_cast<const float4*>(g_xT + d0 * BATCH);
        #pragma unroll
        for (int i = 0; i < (DCHUNK * BATCH / 4) / 128; i++)
            xs4[tid + i * 128] = xg4[tid + i * 128];
        {
            float w0 = W [(n0 + 0) * D_MODEL + d0 + tid];
            float p0 = Bp[(n0 + 0) * D_MODEL + d0 + tid];
            rB_sh[0][tid] = make_float2(__fdividef(1.0f, 1.0f + fabsf(w0)), p0);
            float w1 = W [(n0 + 1) * D_MODEL + d0 + tid];
            float p1 = Bp[(n0 + 1) * D_MODEL + d0 + tid];
            rB_sh[1][tid] = make_float2(__fdividef(1.0f, 1.0f + fabsf(w1)), p1);
        }
        __syncthreads();

        #pragma unroll
        for (int dd = 0; dd < DCHUNK; dd += 4) {
            #pragma unroll
            for (int j = 0; j < 3; j++) {          // 3 MUFU-path elements
                float2 rb = rB_sh[nl][dd + j];
                float th  = fmaf(x_sh[dd + j][b], rb.x, rb.y) + tb;
                float s, c;
                __sincosf(th, &s, &c);
                cs += c; sn += s;
            }
            {                                       // 1 FMA-pipe poly element
                float2 rb = rB_sh[nl][dd + 3];
                float th  = fmaf(x_sh[dd + 3][b], rb.x, rb.y) + tb;
                float s, c;
                sincos_poly(th, s, c);
                cs += c; sn += s;
            }
        }
        __syncthreads();
    }

    int n = n0 + nl;
    g_S[n * BATCH + b]                 = cs;  // cos row: k = n
    g_S[(n + NUM_NEURONS) * BATCH + b] = sn;  // sin row: k = n + 2048
}

// ---------------------------------------------------------------------------
// GEMM: C[b][j] = sum_k S[k][b] * Pcat[j][k], K=4096 split 32 ways.
// 64x64 tile, 4x4 register tile, register double-buffered global staging.
// Partials disjoint per (jt, ks) -> deterministic, no atomics. (R3-proven.)
// ---------------------------------------------------------------------------
__global__ __launch_bounds__(256) void gemm_kernel(const float* __restrict__ Pr,
                                                   const float* __restrict__ Pi) {
    __shared__ float S_sh[32][64];
    __shared__ float P_sh[32][68];   // padded rows, 16B-aligned

    int tid = threadIdx.x;
    int tx  = tid & 15;   // j groups of 4
    int ty  = tid >> 4;   // b groups of 4
    int j0  = blockIdx.x * 64;
    int k0  = blockIdx.y * KCHUNK;

    const float* P     = (k0 < NUM_NEURONS) ? Pr : Pi;
    int          kbase = (k0 < NUM_NEURONS) ? k0 : k0 - NUM_NEURONS;

    int s_lin = tid;          // 2 float4 per thread for S stage
    int jl    = tid >> 2;     // P stage: one j row, 8 contiguous k
    int kk0   = (tid & 3) * 8;

    float4 sA, sB, pA, pB;
    {   // preload chunk 0
        const float4* sg = reinterpret_cast<const float4*>(g_S + k0 * BATCH);
        sA = sg[s_lin]; sB = sg[s_lin + 256];
        const float4* pg = reinterpret_cast<const float4*>(
            P + (j0 + jl) * NUM_NEURONS + kbase + kk0);
        pA = pg[0]; pB = pg[1];
    }

    float acc[4][4] = {};

    #pragma unroll
    for (int kc = 0; kc < KCHUNK; kc += 32) {
        __syncthreads();
        reinterpret_cast<float4*>(&S_sh[0][0])[s_lin]       = sA;
        reinterpret_cast<float4*>(&S_sh[0][0])[s_lin + 256] = sB;
        P_sh[kk0 + 0][jl] = pA.x; P_sh[kk0 + 1][jl] = pA.y;
        P_sh[kk0 + 2][jl] = pA.z; P_sh[kk0 + 3][jl] = pA.w;
        P_sh[kk0 + 4][jl] = pB.x; P_sh[kk0 + 5][jl] = pB.y;
        P_sh[kk0 + 6][jl] = pB.z; P_sh[kk0 + 7][jl] = pB.w;
        __syncthreads();

        if (kc + 32 < KCHUNK) {   // prefetch next chunk into registers
            const float4* sg = reinterpret_cast<const float4*>(g_S + (k0 + kc + 32) * BATCH);
            sA = sg[s_lin]; sB = sg[s_lin + 256];
            const float4* pg = reinterpret_cast<const float4*>(
                P + (j0 + jl) * NUM_NEURONS + kbase + kc + 32 + kk0);
            pA = pg[0]; pB = pg[1];
        }

        #pragma unroll
        for (int kk = 0; kk < 32; kk++) {
            float4 a = *reinterpret_cast<const float4*>(&S_sh[kk][ty * 4]);
            float4 p = *reinterpret_cast<const float4*>(&P_sh[kk][tx * 4]);
            float av[4] = {a.x, a.y, a.z, a.w};
            float pv[4] = {p.x, p.y, p.z, p.w};
            #pragma unroll
            for (int ii = 0; ii < 4; ii++)
                #pragma unroll
                for (int jj = 0; jj < 4; jj++)
                    acc[ii][jj] = fmaf(av[ii], pv[jj], acc[ii][jj]);
        }
    }

    float* dst = g_part + blockIdx.y * (BATCH * D_MODEL);
    #pragma unroll
    for (int ii = 0; ii < 4; ii++) {
        float4 v = make_float4(acc[ii][0], acc[ii][1], acc[ii][2], acc[ii][3]);
        *reinterpret_cast<float4*>(dst + (ty * 4 + ii) * D_MODEL + j0 + tx * 4) = v;
    }
}

// ---------------------------------------------------------------------------
// Epilogue: reduce K-split partials + SiLU. float4 per thread (MLP=32), but
// blockDim=64 so grid = 256 CTAs (> 148 SMs). R4's 64-CTA version regressed.
// ---------------------------------------------------------------------------
__global__ __launch_bounds__(64) void epilogue(float* __restrict__ out) {
    int i4 = blockIdx.x * 64 + threadIdx.x;   // 16384 float4 outputs
    float4 s = make_float4(0.f, 0.f, 0.f, 0.f);
    #pragma unroll
    for (int ks = 0; ks < KSPLIT; ks++) {
        float4 v = reinterpret_cast<const float4*>(g_part + ks * (BATCH * D_MODEL))[i4];
        s.x += v.x; s.y += v.y; s.z += v.z; s.w += v.w;
    }
    float4 o;
    o.x = s.x / (1.0f + expf(-s.x));
    o.y = s.y / (1.0f + expf(-s.y));
    o.z = s.z / (1.0f + expf(-s.z));
    o.w = s.w / (1.0f + expf(-s.w));
    reinterpret_cast<float4*>(out)[i4] = o;
}

// ---------------------------------------------------------------------------
// Inputs: x, t, W, B_p, proj_real_w, proj_imag_w, sin_table, cos_table.
// Tables unused: HW sincos / poly within ~4e-6 abs of the LUT-lerp reference.
// Single stream (R2: chunked multi-stream overlap destroyed occupancy).
// ---------------------------------------------------------------------------
extern "C" void kernel_launch(void* const* d_in, const int* in_sizes, int n_in,
                              void* d_out, int out_size) {
    const float* x  = (const float*)d_in[0];
    const float* t  = (const float*)d_in[1];
    const float* W  = (const float*)d_in[2];
    const float* Bp = (const float*)d_in[3];
    const float* Pr = (const float*)d_in[4];
    const float* Pi = (const float*)d_in[5];
    float* out = (float*)d_out;

    prep_x<<<(BATCH * D_MODEL + 255) / 256, 256>>>(x);
    resonant_main<<<NUM_NEURONS / 2, 128>>>(t, W, Bp);
    dim3 gg(D_MODEL / 64, KSPLIT);
    gemm_kernel<<<gg, 256>>>(Pr, Pi);
    epilogue<<<(BATCH * D_MODEL / 4) / 64, 64>>>(out);
}